// round 2
// baseline (speedup 1.0000x reference)
#include <cuda_runtime.h>
#include <math.h>

// GGNN + Set2Set, fully fused: one CTA per graph (320 graphs x 200 nodes x 64 dim,
// 3200 intra-graph edges). All state lives in SMEM for the whole forward pass.

#define NPG   200      // nodes per graph
#define EPG   3200     // edges per graph
#define DD    64       // feature dim
#define NET   6        // edge types
#define ROWP  65       // padded row stride (floats) for node buffers
#define WPITCH 68      // padded row stride (floats) for weight tile (16B-aligned rows)

// SMEM float offsets
#define H_OFF   0
#define A_OFF   13000          // 200*65
#define S_OFF   26000
#define T2_OFF  39000
#define W_OFF   52000          // 64*68 = 4352 floats -> ends 56352
#define ESRC_BYTE (56352*4)    // 3200 bytes (sorted src, uint8)
#define OFF_BYTE  (ESRC_BYTE + 3200)  // uint16[1216]
#define SMEM_BYTES (OFF_BYTE + 1216*2) // 231040

__device__ __forceinline__ float sigf(float x) {
    return 1.0f / (1.0f + __expf(-x));
}
__device__ __forceinline__ float tanhfast(float x) {
    x = fminf(fmaxf(x, -15.0f), 15.0f);
    float e = __expf(2.0f * x);
    return (e - 1.0f) / (e + 1.0f);
}

// Computes, for this thread, a 4x4 output tile of (src[200x64] @ w[64x64]):
// rows n0..n0+3, cols tx*4..tx*4+3. Unguarded SMEM reads for n>=200 are safe
// (they land inside later SMEM regions) — results are discarded at the epilogue.
__device__ __forceinline__ void mm_tile(const float* src, const float* w,
                                        int n0, int tx, float acc[16]) {
#pragma unroll
    for (int i = 0; i < 16; i++) acc[i] = 0.0f;
    const float* sp = src + n0 * ROWP;
#pragma unroll 8
    for (int d = 0; d < 64; d++) {
        float4 wv = *(const float4*)(w + d * WPITCH + tx * 4);
        float x0 = sp[d];
        float x1 = sp[ROWP + d];
        float x2 = sp[2 * ROWP + d];
        float x3 = sp[3 * ROWP + d];
        acc[0]  = fmaf(x0, wv.x, acc[0]);
        acc[1]  = fmaf(x0, wv.y, acc[1]);
        acc[2]  = fmaf(x0, wv.z, acc[2]);
        acc[3]  = fmaf(x0, wv.w, acc[3]);
        acc[4]  = fmaf(x1, wv.x, acc[4]);
        acc[5]  = fmaf(x1, wv.y, acc[5]);
        acc[6]  = fmaf(x1, wv.z, acc[6]);
        acc[7]  = fmaf(x1, wv.w, acc[7]);
        acc[8]  = fmaf(x2, wv.x, acc[8]);
        acc[9]  = fmaf(x2, wv.y, acc[9]);
        acc[10] = fmaf(x2, wv.z, acc[10]);
        acc[11] = fmaf(x2, wv.w, acc[11]);
        acc[12] = fmaf(x3, wv.x, acc[12]);
        acc[13] = fmaf(x3, wv.y, acc[13]);
        acc[14] = fmaf(x3, wv.z, acc[14]);
        acc[15] = fmaf(x3, wv.w, acc[15]);
    }
}

__global__ __launch_bounds__(512, 1)
void ggnn_fused_kernel(
    const float* __restrict__ feats,
    const float* __restrict__ W_edge,   // [6][64][64]
    const float* __restrict__ b_edge,   // [6][64]
    const float* __restrict__ gWih,     // [192][64] (r,z,n)
    const float* __restrict__ gWhh,     // [192][64]
    const float* __restrict__ gbih,     // [192]
    const float* __restrict__ gbhh,     // [192]
    const float* __restrict__ wih0, const float* __restrict__ whh0,
    const float* __restrict__ bih0, const float* __restrict__ bhh0,
    const float* __restrict__ wih1, const float* __restrict__ whh1,
    const float* __restrict__ bih1, const float* __restrict__ bhh1,
    const float* __restrict__ wih2, const float* __restrict__ whh2,
    const float* __restrict__ bih2, const float* __restrict__ bhh2,
    const float* __restrict__ Wp,       // [3][128]
    const float* __restrict__ bp,       // [3]
    const int* __restrict__ g_src,
    const int* __restrict__ g_dst,
    const int* __restrict__ g_ety,
    float* __restrict__ out)
{
    extern __shared__ float smem[];
    float* h_sm  = smem + H_OFF;
    float* a_sm  = smem + A_OFF;
    float* s_sm  = smem + S_OFF;   // also GRU temp t1
    float* t2_sm = smem + T2_OFF;  // GRU temp t2
    float* w_sm  = smem + W_OFF;
    unsigned char*  esrc = (unsigned char*)smem + ESRC_BYTE;
    unsigned short* off  = (unsigned short*)((char*)smem + OFF_BYTE);

    const int tid = threadIdx.x;
    const int g = blockIdx.x;
    const int nbase = g * NPG;
    const int ebase = g * EPG;
    const int tx = tid & 15;
    const int ty = tid >> 4;   // 0..31

    // ---------- load h (feats) + counting sort of edges by (etype, dst) ----------
    {
        int* cnt  = (int*)w_sm;      // 1280 ints
        int* csum = cnt + 1280;      // 256 ints
        for (int i = tid; i < 1280; i += 512) cnt[i] = 0;
        for (int i = tid; i < NPG * DD; i += 512) {
            int n = i >> 6, d = i & 63;
            h_sm[n * ROWP + d] = feats[(nbase + n) * DD + d];
        }
        __syncthreads();
        for (int e = tid; e < EPG; e += 512) {
            int key = g_ety[ebase + e] * NPG + (g_dst[ebase + e] - nbase);
            atomicAdd(&cnt[key], 1);
        }
        __syncthreads();
        // block-wide exclusive scan of cnt[0..1279] -> off (uint16)
        if (tid < 256) {
            int s = 0;
#pragma unroll
            for (int j = 0; j < 5; j++) s += cnt[tid * 5 + j];
            csum[tid] = s;
        }
        __syncthreads();
        if (tid < 32) {
            int s = 0;
#pragma unroll
            for (int j = 0; j < 8; j++) s += csum[tid * 8 + j];
            int v = s;
            for (int o = 1; o < 32; o <<= 1) {
                int u = __shfl_up_sync(0xffffffffu, v, o);
                if (tid >= o) v += u;
            }
            int run = v - s; // exclusive base for this lane's 8 chunks
#pragma unroll
            for (int j = 0; j < 8; j++) {
                int c = csum[tid * 8 + j];
                csum[tid * 8 + j] = run;
                run += c;
            }
        }
        __syncthreads();
        if (tid < 256) {
            int run = csum[tid];
#pragma unroll
            for (int j = 0; j < 5; j++) {
                int idx = tid * 5 + j;
                int c = cnt[idx];
                if (idx < 1216) off[idx] = (unsigned short)run;
                run += c;
            }
        }
        __syncthreads();
        // cursor = bucket starts, then scatter sorted src
        for (int i = tid; i < 1200; i += 512) cnt[i] = off[i];
        __syncthreads();
        for (int e = tid; e < EPG; e += 512) {
            int key = g_ety[ebase + e] * NPG + (g_dst[ebase + e] - nbase);
            int pos = atomicAdd(&cnt[key], 1);
            esrc[pos] = (unsigned char)(g_src[ebase + e] - nbase);
        }
        __syncthreads();
    }

    // ---------- GatedGraphConv: 5 steps ----------
    for (int step = 0; step < 5; step++) {
        // a = sum_t (S_t @ W_t + cnt_t * b_t)
        for (int t = 0; t < NET; t++) {
            __syncthreads(); // protect w_sm/s_sm from previous pass readers
            // load W_edge[t] (layout [d][o], no transpose)
            for (int i = tid; i < 4096; i += 512) {
                int d = i >> 6, o = i & 63;
                w_sm[d * WPITCH + o] = W_edge[(t * 64 + d) * 64 + o];
            }
            // aggregate s[n][d] = sum over etype-t edges with dst n of h[src][d]
            {
                int d = tid & 63, nb = tid >> 6; // nb 0..7
                for (int n = nb; n < NPG; n += 8) {
                    int b = t * NPG + n;
                    int j0 = off[b], j1 = off[b + 1];
                    float acc = 0.0f;
                    for (int j = j0; j < j1; j++)
                        acc += h_sm[(int)esrc[j] * ROWP + d];
                    s_sm[n * ROWP + d] = acc;
                }
            }
            __syncthreads();
            // a (+)= s @ W_t + cnt * b_t
            float be[4];
#pragma unroll
            for (int j = 0; j < 4; j++) be[j] = b_edge[t * 64 + tx * 4 + j];
#pragma unroll
            for (int slab = 0; slab < 2; slab++) {
                int n0 = slab * 128 + ty * 4;
                float acc[16];
                mm_tile(s_sm, w_sm, n0, tx, acc);
#pragma unroll
                for (int i = 0; i < 4; i++) {
                    int n = n0 + i;
                    if (n < NPG) {
                        float cf = (float)(off[t * NPG + n + 1] - off[t * NPG + n]);
#pragma unroll
                        for (int j = 0; j < 4; j++) {
                            int k = tx * 4 + j;
                            float v = acc[i * 4 + j] + cf * be[j];
                            if (t == 0) a_sm[n * ROWP + k] = v;
                            else        a_sm[n * ROWP + k] += v;
                        }
                    }
                }
            }
        }

        // ---- GRU ----
        float* t1 = s_sm;
        // helper pattern: sync; load transposed weight chunk; sync; mm; epilogue
#define GRU_LOADW(MAT, G0)                                              \
        __syncthreads();                                                \
        for (int i = tid; i < 4096; i += 512) {                         \
            int k = i >> 6, d = i & 63;                                 \
            w_sm[d * WPITCH + k] = (MAT)[((G0) + k) * 64 + d];          \
        }                                                               \
        __syncthreads();

        // pass 1: t1 = a @ Wih_r
        GRU_LOADW(gWih, 0)
#pragma unroll
        for (int slab = 0; slab < 2; slab++) {
            int n0 = slab * 128 + ty * 4;
            float acc[16];
            mm_tile(a_sm, w_sm, n0, tx, acc);
#pragma unroll
            for (int i = 0; i < 4; i++) {
                int n = n0 + i;
                if (n < NPG)
#pragma unroll
                    for (int j = 0; j < 4; j++)
                        t1[n * ROWP + tx * 4 + j] = acc[i * 4 + j];
            }
        }
        // pass 2: t1 = sigmoid(t1 + h @ Whh_r + b_ih_r + b_hh_r)
        GRU_LOADW(gWhh, 0)
        {
            float b1[4], b2[4];
#pragma unroll
            for (int j = 0; j < 4; j++) { b1[j] = gbih[tx * 4 + j]; b2[j] = gbhh[tx * 4 + j]; }
#pragma unroll
            for (int slab = 0; slab < 2; slab++) {
                int n0 = slab * 128 + ty * 4;
                float acc[16];
                mm_tile(h_sm, w_sm, n0, tx, acc);
#pragma unroll
                for (int i = 0; i < 4; i++) {
                    int n = n0 + i;
                    if (n < NPG)
#pragma unroll
                        for (int j = 0; j < 4; j++) {
                            int k = tx * 4 + j;
                            t1[n * ROWP + k] = sigf(t1[n * ROWP + k] + acc[i * 4 + j] + b1[j] + b2[j]);
                        }
                }
            }
        }
        // pass 3: t2 = h @ Whh_n (raw)
        GRU_LOADW(gWhh, 128)
#pragma unroll
        for (int slab = 0; slab < 2; slab++) {
            int n0 = slab * 128 + ty * 4;
            float acc[16];
            mm_tile(h_sm, w_sm, n0, tx, acc);
#pragma unroll
            for (int i = 0; i < 4; i++) {
                int n = n0 + i;
                if (n < NPG)
#pragma unroll
                    for (int j = 0; j < 4; j++)
                        t2_sm[n * ROWP + tx * 4 + j] = acc[i * 4 + j];
            }
        }
        // pass 4: t2 = tanh(a@Wih_n + b_ih_n + r * (t2 + b_hh_n))
        GRU_LOADW(gWih, 128)
        {
            float b1[4], b2[4];
#pragma unroll
            for (int j = 0; j < 4; j++) { b1[j] = gbih[128 + tx * 4 + j]; b2[j] = gbhh[128 + tx * 4 + j]; }
#pragma unroll
            for (int slab = 0; slab < 2; slab++) {
                int n0 = slab * 128 + ty * 4;
                float acc[16];
                mm_tile(a_sm, w_sm, n0, tx, acc);
#pragma unroll
                for (int i = 0; i < 4; i++) {
                    int n = n0 + i;
                    if (n < NPG)
#pragma unroll
                        for (int j = 0; j < 4; j++) {
                            int k = tx * 4 + j;
                            float r = t1[n * ROWP + k];
                            t2_sm[n * ROWP + k] =
                                tanhfast(acc[i * 4 + j] + b1[j] + r * (t2_sm[n * ROWP + k] + b2[j]));
                        }
                }
            }
        }
        // pass 5: t1 = a @ Wih_z (raw)
        GRU_LOADW(gWih, 64)
#pragma unroll
        for (int slab = 0; slab < 2; slab++) {
            int n0 = slab * 128 + ty * 4;
            float acc[16];
            mm_tile(a_sm, w_sm, n0, tx, acc);
#pragma unroll
            for (int i = 0; i < 4; i++) {
                int n = n0 + i;
                if (n < NPG)
#pragma unroll
                    for (int j = 0; j < 4; j++)
                        t1[n * ROWP + tx * 4 + j] = acc[i * 4 + j];
            }
        }
        // pass 6: t1 = sigmoid(t1 + h @ Whh_z + biases)  -> z
        GRU_LOADW(gWhh, 64)
        {
            float b1[4], b2[4];
#pragma unroll
            for (int j = 0; j < 4; j++) { b1[j] = gbih[64 + tx * 4 + j]; b2[j] = gbhh[64 + tx * 4 + j]; }
#pragma unroll
            for (int slab = 0; slab < 2; slab++) {
                int n0 = slab * 128 + ty * 4;
                float acc[16];
                mm_tile(h_sm, w_sm, n0, tx, acc);
#pragma unroll
                for (int i = 0; i < 4; i++) {
                    int n = n0 + i;
                    if (n < NPG)
#pragma unroll
                        for (int j = 0; j < 4; j++) {
                            int k = tx * 4 + j;
                            t1[n * ROWP + k] = sigf(t1[n * ROWP + k] + acc[i * 4 + j] + b1[j] + b2[j]);
                        }
                }
            }
        }
        __syncthreads();
        // h = (1 - z) * n + z * h
        for (int i = tid; i < NPG * DD; i += 512) {
            int n = i >> 6, d = i & 63;
            int idx = n * ROWP + d;
            float z = t1[idx];
            h_sm[idx] = (1.0f - z) * t2_sm[idx] + z * h_sm[idx];
        }
        __syncthreads();
    }

    // ---------- Set2Set readout ----------
    float* qstar = a_sm;        // 128
    float* hL    = a_sm + 128;  // 3*64
    float* cL    = a_sm + 320;  // 3*64
    float* gates = a_sm + 512;  // 256
    float* red   = a_sm + 768;  // 32
    float* alpha = s_sm;        // 200

    for (int i = tid; i < 512; i += 512) a_sm[i] = 0.0f;
    __syncthreads();

    const float* WiA[3]  = { wih0, wih1, wih2 };
    const float* WhA[3]  = { whh0, whh1, whh2 };
    const float* biA[3]  = { bih0, bih1, bih2 };
    const float* bhA[3]  = { bhh0, bhh1, bhh2 };

    const int lane = tid & 31;
    const int wid = tid >> 5;

    for (int it = 0; it < 6; it++) {
        // 3-layer LSTM on this graph's row
        for (int l = 0; l < 3; l++) {
            const float* xin = (l == 0) ? qstar : (hL + (l - 1) * 64);
            int indim = (l == 0) ? 128 : 64;
            if (tid < 256) {
                float acc = biA[l][tid] + bhA[l][tid];
                const float* wr = WiA[l] + tid * indim;
                for (int j = 0; j < indim; j += 4) {
                    float4 wv = *(const float4*)(wr + j);
                    acc += xin[j] * wv.x + xin[j + 1] * wv.y + xin[j + 2] * wv.z + xin[j + 3] * wv.w;
                }
                const float* wr2 = WhA[l] + tid * 64;
                const float* hin = hL + l * 64;
                for (int j = 0; j < 64; j += 4) {
                    float4 wv = *(const float4*)(wr2 + j);
                    acc += hin[j] * wv.x + hin[j + 1] * wv.y + hin[j + 2] * wv.z + hin[j + 3] * wv.w;
                }
                gates[tid] = acc;
            }
            __syncthreads();
            if (tid < 64) {
                float gi = gates[tid], gf = gates[64 + tid], gg = gates[128 + tid], go = gates[192 + tid];
                float c = sigf(gf) * cL[l * 64 + tid] + sigf(gi) * tanhfast(gg);
                cL[l * 64 + tid] = c;
                hL[l * 64 + tid] = sigf(go) * tanhfast(c);
            }
            __syncthreads();
        }
        // attention over this graph's 200 nodes; q = hL[2]
        const float* q = hL + 128;
        float e = -3.4e38f;
        if (tid < NPG) {
            float acc = 0.0f;
            for (int d = 0; d < 64; d++) acc += h_sm[tid * ROWP + d] * q[d];
            e = acc;
        }
        float m = e;
#pragma unroll
        for (int o = 16; o >= 1; o >>= 1) m = fmaxf(m, __shfl_xor_sync(0xffffffffu, m, o));
        if (lane == 0) red[wid] = m;
        __syncthreads();
        if (tid == 0) {
            float mm = red[0];
            for (int w = 1; w < 16; w++) mm = fmaxf(mm, red[w]);
            red[16] = mm;
        }
        __syncthreads();
        float bmax = red[16];
        float ex = (tid < NPG) ? __expf(e - bmax) : 0.0f;
        float ssum = ex;
#pragma unroll
        for (int o = 16; o >= 1; o >>= 1) ssum += __shfl_xor_sync(0xffffffffu, ssum, o);
        if (lane == 0) red[wid] = ssum;
        __syncthreads();
        if (tid == 0) {
            float sm = 0.0f;
            for (int w = 0; w < 16; w++) sm += red[w];
            red[17] = sm;
        }
        __syncthreads();
        float denom = red[17];
        if (tid < NPG) alpha[tid] = ex / denom;
        __syncthreads();
        if (tid < 64) {
            float acc = 0.0f;
            for (int n = 0; n < NPG; n++) acc += h_sm[n * ROWP + tid] * alpha[n];
            qstar[64 + tid] = acc;
            qstar[tid] = q[tid];
        }
        __syncthreads();
    }

    // final projection: out[g] = q_star @ Wp^T + bp  (3 outputs)
    if (tid < 3) {
        float acc = bp[tid];
        for (int j = 0; j < 128; j++) acc += qstar[j] * Wp[tid * 128 + j];
        out[g * 3 + tid] = acc;
    }
}

extern "C" void kernel_launch(void* const* d_in, const int* in_sizes, int n_in,
                              void* d_out, int out_size) {
    const float* feats  = (const float*)d_in[0];
    const float* W_edge = (const float*)d_in[1];
    const float* b_edge = (const float*)d_in[2];
    const float* gWih   = (const float*)d_in[3];
    const float* gWhh   = (const float*)d_in[4];
    const float* gbih   = (const float*)d_in[5];
    const float* gbhh   = (const float*)d_in[6];
    const float* wih0 = (const float*)d_in[7];
    const float* whh0 = (const float*)d_in[8];
    const float* bih0 = (const float*)d_in[9];
    const float* bhh0 = (const float*)d_in[10];
    const float* wih1 = (const float*)d_in[11];
    const float* whh1 = (const float*)d_in[12];
    const float* bih1 = (const float*)d_in[13];
    const float* bhh1 = (const float*)d_in[14];
    const float* wih2 = (const float*)d_in[15];
    const float* whh2 = (const float*)d_in[16];
    const float* bih2 = (const float*)d_in[17];
    const float* bhh2 = (const float*)d_in[18];
    const float* Wp   = (const float*)d_in[19];
    const float* bp   = (const float*)d_in[20];
    const int* src    = (const int*)d_in[21];
    const int* dst    = (const int*)d_in[22];
    const int* ety    = (const int*)d_in[23];
    float* out = (float*)d_out;

    cudaFuncSetAttribute(ggnn_fused_kernel,
                         cudaFuncAttributeMaxDynamicSharedMemorySize, SMEM_BYTES);

    ggnn_fused_kernel<<<320, 512, SMEM_BYTES>>>(
        feats, W_edge, b_edge, gWih, gWhh, gbih, gbhh,
        wih0, whh0, bih0, bhh0,
        wih1, whh1, bih1, bhh1,
        wih2, whh2, bih2, bhh2,
        Wp, bp, src, dst, ety, out);
}

// round 3
// speedup vs baseline: 1.2159x; 1.2159x over previous
#include <cuda_runtime.h>
#include <math.h>

// GGNN + Set2Set, fully fused: one CTA per graph (320 graphs x 200 nodes x 64 dim,
// 3200 intra-graph edges). All state in SMEM. 640 threads, 5x4 register tiles
// (zero wasted FMA), rotation-swizzled pitch-64 node buffers (float4 both sides).

#define NPG   200
#define EPG   3200
#define NET   6
#define NTH   640

// SMEM float offsets (pitch 64, swizzled)
#define H_OFF   0
#define A_OFF   12800
#define S_OFF   25600          // also GRU temp t1
#define T2_OFF  38400
#define W_OFF   51200          // 64x64 weight tile (swizzled) -> ends 55296
#define ESRC_BYTE (55296*4)    // 3200 bytes sorted src (uint8)
#define OFF_BYTE  (ESRC_BYTE + 3200)
#define SMEM_BYTES (OFF_BYTE + 1216*2)   // 226816 <= 232448

// logical float4-column c4 of row stored at physical slot ((c4+row)&15)
#define SWZ4(row, c4) (((row)<<6) + ((((c4)+(row))&15)<<2))

__device__ __forceinline__ float sigf(float x) { return 1.0f / (1.0f + __expf(-x)); }
__device__ __forceinline__ float tanhfast(float x) {
    x = fminf(fmaxf(x, -15.0f), 15.0f);
    float e = __expf(2.0f * x);
    return (e - 1.0f) / (e + 1.0f);
}

// 5x4 output tile of (src[200x64] @ w[64x64]); rows r0..r0+4, cols tx*4..tx*4+3.
// Both src and w are rotation-swizzled.
__device__ __forceinline__ void mm5(const float* __restrict__ src,
                                    const float* __restrict__ w,
                                    int r0, int tx, float* acc) {
#pragma unroll
    for (int i = 0; i < 20; i++) acc[i] = 0.0f;
#pragma unroll 4
    for (int db = 0; db < 16; db++) {
        int d0 = db * 4;
        float4 w0 = *(const float4*)(w + SWZ4(d0 + 0, tx));
        float4 w1 = *(const float4*)(w + SWZ4(d0 + 1, tx));
        float4 w2 = *(const float4*)(w + SWZ4(d0 + 2, tx));
        float4 w3 = *(const float4*)(w + SWZ4(d0 + 3, tx));
#pragma unroll
        for (int r = 0; r < 5; r++) {
            float4 xv = *(const float4*)(src + SWZ4(r0 + r, db));
            acc[r*4+0] = fmaf(xv.x, w0.x, fmaf(xv.y, w1.x, fmaf(xv.z, w2.x, fmaf(xv.w, w3.x, acc[r*4+0]))));
            acc[r*4+1] = fmaf(xv.x, w0.y, fmaf(xv.y, w1.y, fmaf(xv.z, w2.y, fmaf(xv.w, w3.y, acc[r*4+1]))));
            acc[r*4+2] = fmaf(xv.x, w0.z, fmaf(xv.y, w1.z, fmaf(xv.z, w2.z, fmaf(xv.w, w3.z, acc[r*4+2]))));
            acc[r*4+3] = fmaf(xv.x, w0.w, fmaf(xv.y, w1.w, fmaf(xv.z, w2.w, fmaf(xv.w, w3.w, acc[r*4+3]))));
        }
    }
}

__global__ __launch_bounds__(NTH, 1)
void ggnn_fused_kernel(
    const float* __restrict__ feats,
    const float* __restrict__ W_edge,   // [6][64][64]
    const float* __restrict__ b_edge,   // [6][64]
    const float* __restrict__ gWih,     // [192][64] (r,z,n)
    const float* __restrict__ gWhh,     // [192][64]
    const float* __restrict__ gbih,
    const float* __restrict__ gbhh,
    const float* __restrict__ wih0, const float* __restrict__ whh0,
    const float* __restrict__ bih0, const float* __restrict__ bhh0,
    const float* __restrict__ wih1, const float* __restrict__ whh1,
    const float* __restrict__ bih1, const float* __restrict__ bhh1,
    const float* __restrict__ wih2, const float* __restrict__ whh2,
    const float* __restrict__ bih2, const float* __restrict__ bhh2,
    const float* __restrict__ Wp,       // [3][128]
    const float* __restrict__ bp,       // [3]
    const int* __restrict__ g_src,
    const int* __restrict__ g_dst,
    const int* __restrict__ g_ety,
    float* __restrict__ out)
{
    extern __shared__ float smem[];
    float* h_sm  = smem + H_OFF;
    float* a_sm  = smem + A_OFF;
    float* s_sm  = smem + S_OFF;   // also t1
    float* t2_sm = smem + T2_OFF;
    float* w_sm  = smem + W_OFF;
    unsigned char*  esrc = (unsigned char*)smem + ESRC_BYTE;
    unsigned short* off  = (unsigned short*)((char*)smem + OFF_BYTE);

    const int tid = threadIdx.x;
    const int g = blockIdx.x;
    const int nbase = g * NPG;
    const int ebase = g * EPG;
    const int tx = tid & 15;
    const int rt = tid >> 4;      // 0..39
    const int r0 = rt * 5;        // rows r0..r0+4 (exactly covers 200)

    // ---------- load feats (swizzled) + counting sort of edges by (etype, dst) ----------
    {
        int* cnt  = (int*)w_sm;      // 1280 ints
        int* csum = cnt + 1280;      // 256 ints
        for (int i = tid; i < 1280; i += NTH) cnt[i] = 0;
        for (int i = tid; i < NPG * 64; i += NTH) {
            int n = i >> 6, d = i & 63;
            h_sm[SWZ4(n, d >> 2) + (d & 3)] = feats[(nbase + n) * 64 + d];
        }
        __syncthreads();
        for (int e = tid; e < EPG; e += NTH) {
            int key = g_ety[ebase + e] * NPG + (g_dst[ebase + e] - nbase);
            atomicAdd(&cnt[key], 1);
        }
        __syncthreads();
        if (tid < 256) {
            int s = 0;
#pragma unroll
            for (int j = 0; j < 5; j++) s += cnt[tid * 5 + j];
            csum[tid] = s;
        }
        __syncthreads();
        if (tid < 32) {
            int s = 0;
#pragma unroll
            for (int j = 0; j < 8; j++) s += csum[tid * 8 + j];
            int v = s;
            for (int o = 1; o < 32; o <<= 1) {
                int u = __shfl_up_sync(0xffffffffu, v, o);
                if (tid >= o) v += u;
            }
            int run = v - s;
#pragma unroll
            for (int j = 0; j < 8; j++) {
                int c = csum[tid * 8 + j];
                csum[tid * 8 + j] = run;
                run += c;
            }
        }
        __syncthreads();
        if (tid < 256) {
            int run = csum[tid];
#pragma unroll
            for (int j = 0; j < 5; j++) {
                int idx = tid * 5 + j;
                int c = cnt[idx];
                if (idx < 1216) off[idx] = (unsigned short)run;
                run += c;
            }
        }
        __syncthreads();
        for (int i = tid; i < 1200; i += NTH) cnt[i] = off[i];
        __syncthreads();
        for (int e = tid; e < EPG; e += NTH) {
            int key = g_ety[ebase + e] * NPG + (g_dst[ebase + e] - nbase);
            int pos = atomicAdd(&cnt[key], 1);
            esrc[pos] = (unsigned char)(g_src[ebase + e] - nbase);
        }
    }

    // ---------- GatedGraphConv: 5 steps ----------
    for (int step = 0; step < 5; step++) {
        // a = sum_t (S_t @ W_t + cnt_t * b_t)
        for (int t = 0; t < NET; t++) {
            __syncthreads();   // previous readers of w_sm / s_sm done
            // load W_edge[t] (no transpose), swizzled
            for (int i = tid; i < 4096; i += NTH) {
                int d = i >> 6, o = i & 63;
                w_sm[SWZ4(d, o >> 2) + (o & 3)] = W_edge[(t * 64 + d) * 64 + o];
            }
            // aggregate s[n][:] = sum over etype-t edges with dst n of h[src][:]
            {
                int dg = tid & 15, ns = tid >> 4;
                for (int n = ns; n < NPG; n += 40) {
                    int b = t * NPG + n;
                    int j0 = off[b], j1 = off[b + 1];
                    float4 acc4 = make_float4(0.f, 0.f, 0.f, 0.f);
                    for (int j = j0; j < j1; j++) {
                        float4 v = *(const float4*)(h_sm + SWZ4((int)esrc[j], dg));
                        acc4.x += v.x; acc4.y += v.y; acc4.z += v.z; acc4.w += v.w;
                    }
                    *(float4*)(s_sm + SWZ4(n, dg)) = acc4;
                }
            }
            __syncthreads();
            float4 be = *(const float4*)(b_edge + t * 64 + tx * 4);
            float acc[20];
            mm5(s_sm, w_sm, r0, tx, acc);
#pragma unroll
            for (int r = 0; r < 5; r++) {
                int row = r0 + r;
                float cf = (float)(off[t * NPG + row + 1] - off[t * NPG + row]);
                float4* ap = (float4*)(a_sm + SWZ4(row, tx));
                float4 v;
                v.x = fmaf(cf, be.x, acc[r*4+0]);
                v.y = fmaf(cf, be.y, acc[r*4+1]);
                v.z = fmaf(cf, be.z, acc[r*4+2]);
                v.w = fmaf(cf, be.w, acc[r*4+3]);
                if (t == 0) *ap = v;
                else { float4 o = *ap; o.x += v.x; o.y += v.y; o.z += v.z; o.w += v.w; *ap = o; }
            }
        }

        // ---- GRU: 6 table-driven passes (one code instance) ----
        {
            const float* mats[6] = { gWih, gWhh, gWhh, gWih, gWih, gWhh };
            const int    g0s[6]  = { 0, 0, 128, 128, 64, 64 };
            const float* srcs[6] = { a_sm, h_sm, h_sm, a_sm, a_sm, h_sm };
            float* t1 = s_sm;
            for (int p = 0; p < 6; p++) {
                __syncthreads();
                const float* M = mats[p];
                const int g0 = g0s[p];
                for (int i = tid; i < 4096; i += NTH) {
                    int k = i >> 6, d = i & 63;     // w_sm[d][k] = M[g0+k][d]
                    w_sm[SWZ4(d, k >> 2) + (k & 3)] = M[(g0 + k) * 64 + d];
                }
                __syncthreads();
                float acc[20];
                mm5(srcs[p], w_sm, r0, tx, acc);
                if (p == 0 || p == 4) {            // raw store -> t1
#pragma unroll
                    for (int r = 0; r < 5; r++) {
                        float4 v = make_float4(acc[r*4+0], acc[r*4+1], acc[r*4+2], acc[r*4+3]);
                        *(float4*)(t1 + SWZ4(r0 + r, tx)) = v;
                    }
                } else if (p == 2) {               // raw store -> t2
#pragma unroll
                    for (int r = 0; r < 5; r++) {
                        float4 v = make_float4(acc[r*4+0], acc[r*4+1], acc[r*4+2], acc[r*4+3]);
                        *(float4*)(t2_sm + SWZ4(r0 + r, tx)) = v;
                    }
                } else if (p == 1 || p == 5) {     // gate = sigmoid(t1 + acc + biases)
                    int b0 = (p == 1) ? 0 : 64;
                    float4 b1 = *(const float4*)(gbih + b0 + tx * 4);
                    float4 b2 = *(const float4*)(gbhh + b0 + tx * 4);
#pragma unroll
                    for (int r = 0; r < 5; r++) {
                        float4* tp = (float4*)(t1 + SWZ4(r0 + r, tx));
                        float4 o = *tp;
                        o.x = sigf(o.x + acc[r*4+0] + b1.x + b2.x);
                        o.y = sigf(o.y + acc[r*4+1] + b1.y + b2.y);
                        o.z = sigf(o.z + acc[r*4+2] + b1.z + b2.z);
                        o.w = sigf(o.w + acc[r*4+3] + b1.w + b2.w);
                        *tp = o;
                    }
                } else {                           // p==3: n = tanh(acc + bih_n + r*(t2 + bhh_n))
                    float4 b1 = *(const float4*)(gbih + 128 + tx * 4);
                    float4 b2 = *(const float4*)(gbhh + 128 + tx * 4);
#pragma unroll
                    for (int r = 0; r < 5; r++) {
                        float4* tp = (float4*)(t2_sm + SWZ4(r0 + r, tx));
                        float4 rg = *(const float4*)(t1 + SWZ4(r0 + r, tx));
                        float4 o = *tp;
                        o.x = tanhfast(acc[r*4+0] + b1.x + rg.x * (o.x + b2.x));
                        o.y = tanhfast(acc[r*4+1] + b1.y + rg.y * (o.y + b2.y));
                        o.z = tanhfast(acc[r*4+2] + b1.z + rg.z * (o.z + b2.z));
                        o.w = tanhfast(acc[r*4+3] + b1.w + rg.w * (o.w + b2.w));
                        *tp = o;
                    }
                }
            }
        }
        __syncthreads();
        // h = (1 - z) * n + z * h   (t1 = z, t2 = n; identical layout across buffers)
        for (int i = tid; i < NPG * 64; i += NTH) {
            float z = s_sm[i];
            h_sm[i] = (1.0f - z) * t2_sm[i] + z * h_sm[i];
        }
    }
    __syncthreads();

    // ---------- Set2Set readout ----------
    float* qstar = a_sm;         // 128
    float* hL    = a_sm + 128;   // 192
    float* cL    = a_sm + 320;   // 192
    float* gates = a_sm + 512;   // 256
    float* red   = a_sm + 768;   // 32
    float* part  = a_sm + 800;   // 640
    float* evals = s_sm;         // 200 (alpha)

    for (int i = tid; i < 512; i += NTH) a_sm[i] = 0.0f;
    __syncthreads();

    const float* WiA[3] = { wih0, wih1, wih2 };
    const float* WhA[3] = { whh0, whh1, whh2 };
    const float* biA[3] = { bih0, bih1, bih2 };
    const float* bhA[3] = { bhh0, bhh1, bhh2 };

    const int lane = tid & 31;
    const int wid = tid >> 5;    // 0..19

    for (int it = 0; it < 6; it++) {
        // 3-layer LSTM
        for (int l = 0; l < 3; l++) {
            const float* xin = (l == 0) ? qstar : (hL + (l - 1) * 64);
            int indim = (l == 0) ? 128 : 64;
            if (tid < 256) {
                float acc = biA[l][tid] + bhA[l][tid];
                const float* wr = WiA[l] + tid * indim;
                for (int j = 0; j < indim; j += 4) {
                    float4 wv = *(const float4*)(wr + j);
                    acc += xin[j] * wv.x + xin[j+1] * wv.y + xin[j+2] * wv.z + xin[j+3] * wv.w;
                }
                const float* wr2 = WhA[l] + tid * 64;
                const float* hin = hL + l * 64;
                for (int j = 0; j < 64; j += 4) {
                    float4 wv = *(const float4*)(wr2 + j);
                    acc += hin[j] * wv.x + hin[j+1] * wv.y + hin[j+2] * wv.z + hin[j+3] * wv.w;
                }
                gates[tid] = acc;
            }
            __syncthreads();
            if (tid < 64) {
                float gi = gates[tid], gf = gates[64 + tid], gg = gates[128 + tid], go = gates[192 + tid];
                float c = sigf(gf) * cL[l * 64 + tid] + sigf(gi) * tanhfast(gg);
                cL[l * 64 + tid] = c;
                hL[l * 64 + tid] = sigf(go) * tanhfast(c);
            }
            __syncthreads();
        }
        // attention: e_n = <h_n, q>, segment softmax, weighted readout
        const float* q = hL + 128;
        float e = -3.4e38f;
        if (tid < NPG) {
            float acc = 0.0f;
#pragma unroll 4
            for (int c4 = 0; c4 < 16; c4++) {
                float4 hv = *(const float4*)(h_sm + SWZ4(tid, c4));
                float4 qv = *(const float4*)(q + c4 * 4);
                acc = fmaf(hv.x, qv.x, fmaf(hv.y, qv.y, fmaf(hv.z, qv.z, fmaf(hv.w, qv.w, acc))));
            }
            e = acc;
        }
        float m = e;
#pragma unroll
        for (int o = 16; o >= 1; o >>= 1) m = fmaxf(m, __shfl_xor_sync(0xffffffffu, m, o));
        if (lane == 0) red[wid] = m;
        __syncthreads();
        if (tid == 0) {
            float mm = red[0];
            for (int w = 1; w < 20; w++) mm = fmaxf(mm, red[w]);
            red[24] = mm;
        }
        __syncthreads();
        float bmax = red[24];
        float ex = (tid < NPG) ? __expf(e - bmax) : 0.0f;
        float ssum = ex;
#pragma unroll
        for (int o = 16; o >= 1; o >>= 1) ssum += __shfl_xor_sync(0xffffffffu, ssum, o);
        if (lane == 0) red[wid] = ssum;
        __syncthreads();
        if (tid == 0) {
            float sm = 0.0f;
            for (int w = 0; w < 20; w++) sm += red[w];
            red[25] = sm;
        }
        __syncthreads();
        float denom = red[25];
        if (tid < NPG) evals[tid] = ex / denom;
        __syncthreads();
        // readout = sum_n alpha_n * h_n : 640 threads = 64 dims x 10 node-groups
        {
            int d = tid & 63, grp = tid >> 6;   // grp 0..9
            float acc = 0.0f;
            int nlo = grp * 20;
            for (int n = nlo; n < nlo + 20; n++)
                acc = fmaf(h_sm[SWZ4(n, d >> 2) + (d & 3)], evals[n], acc);
            part[grp * 64 + d] = acc;
        }
        __syncthreads();
        if (tid < 64) {
            float acc = 0.0f;
#pragma unroll
            for (int gg = 0; gg < 10; gg++) acc += part[gg * 64 + tid];
            qstar[64 + tid] = acc;
            qstar[tid] = q[tid];
        }
        __syncthreads();
    }

    // final projection: out[g] = q_star @ Wp^T + bp
    if (tid < 3) {
        float acc = bp[tid];
        for (int j = 0; j < 128; j++) acc = fmaf(qstar[j], Wp[tid * 128 + j], acc);
        out[g * 3 + tid] = acc;
    }
}

extern "C" void kernel_launch(void* const* d_in, const int* in_sizes, int n_in,
                              void* d_out, int out_size) {
    const float* feats  = (const float*)d_in[0];
    const float* W_edge = (const float*)d_in[1];
    const float* b_edge = (const float*)d_in[2];
    const float* gWih   = (const float*)d_in[3];
    const float* gWhh   = (const float*)d_in[4];
    const float* gbih   = (const float*)d_in[5];
    const float* gbhh   = (const float*)d_in[6];
    const float* wih0 = (const float*)d_in[7];
    const float* whh0 = (const float*)d_in[8];
    const float* bih0 = (const float*)d_in[9];
    const float* bhh0 = (const float*)d_in[10];
    const float* wih1 = (const float*)d_in[11];
    const float* whh1 = (const float*)d_in[12];
    const float* bih1 = (const float*)d_in[13];
    const float* bhh1 = (const float*)d_in[14];
    const float* wih2 = (const float*)d_in[15];
    const float* whh2 = (const float*)d_in[16];
    const float* bih2 = (const float*)d_in[17];
    const float* bhh2 = (const float*)d_in[18];
    const float* Wp   = (const float*)d_in[19];
    const float* bp   = (const float*)d_in[20];
    const int* src    = (const int*)d_in[21];
    const int* dst    = (const int*)d_in[22];
    const int* ety    = (const int*)d_in[23];
    float* out = (float*)d_out;

    cudaFuncSetAttribute(ggnn_fused_kernel,
                         cudaFuncAttributeMaxDynamicSharedMemorySize, SMEM_BYTES);

    ggnn_fused_kernel<<<320, NTH, SMEM_BYTES>>>(
        feats, W_edge, b_edge, gWih, gWhh, gbih, gbhh,
        wih0, whh0, bih0, bhh0,
        wih1, whh1, bih1, bhh1,
        wih2, whh2, bih2, bhh2,
        Wp, bp, src, dst, ety, out);
}